// round 8
// baseline (speedup 1.0000x reference)
#include <cuda_runtime.h>
#include <math.h>

#define N_IMG 16
#define H 1024
#define W 1024
#define HW (H * W)
#define TOT (N_IMG * HW)
#define RAD 8
#define KLEN 17
#define NPASS 4
#define WW64 (W / 64)
#define WW32 (W / 32)

typedef unsigned long long ull;

// gaussian(sigma=2,r=8) weights as compile-time literals
__device__ __forceinline__ float gw(int k) {
    switch (k) {
        case 0: case 16: return 6.6916292e-05f;
        case 1: case 15: return 4.3634888e-04f;
        case 2: case 14: return 2.2159620e-03f;
        case 3: case 13: return 8.7643044e-03f;
        case 4: case 12: return 2.6995958e-02f;
        case 5: case 11: return 6.4759926e-02f;
        case 6: case 10: return 1.2098749e-01f;
        case 7: case 9:  return 1.7603576e-01f;
        default:         return 1.9947465e-01f;
    }
}

// ---------------- scratch ----------------
__device__ ull g_strong64[TOT / 64];
__device__ ull g_weak64[TOT / 64];
__device__ double g_acc;
__device__ unsigned char g_blkchg[NPASS][N_IMG][WW64];
__device__ unsigned int g_ticket;

__device__ __forceinline__ int reflect_idx(int i, int n) {
    if (i < 0) return -i;
    if (i >= n) return 2 * n - 2 - i;
    return i;
}

// ---------------- fully fused canny front-end ----------------
// rowblur + colblur + sobel(mag^2) + NMS + thresholds, tile 128 rows x 32 cols
#define TILE_H 128
#define T1R 148          // rows r0-10 .. r0+137
#define XC 56            // x cols c0-12 .. c0+43
#define T1C 40           // rowblurred cols c0-4 .. c0+35
#define SSR 132          // smoothed rows r0-2 .. r0+129
#define MGSTRIDE 36      // mag 130 x 34, stride 36

__device__ __forceinline__ signed char dir_off(float u, float v) {
    if (v < 0.f || (v == 0.f && u < 0.f)) { u = -u; v = -v; }
    const float c1 = 0.41421356237309503f;
    const float c2 = 2.414213562373095f;
    if (u > 0.f) {
        if (v < c1 * u)      return 1;
        else if (v < c2 * u) return -(MGSTRIDE - 1);
        else                 return -MGSTRIDE;
    } else if (u < 0.f) {
        float t = -u;
        if (v <= c1 * t)     return 1;
        else if (v > c2 * t) return -MGSTRIDE;
        else                 return -(MGSTRIDE + 1);
    }
    return -MGSTRIDE;
}

__global__ void __launch_bounds__(256) k_canny(const float* __restrict__ x) {
    __shared__ __align__(16) float sX[T1R * XC];   // raw x tile; later aliased by sS
    __shared__ __align__(16) float sA[T1R * T1C];  // rowblurred; later mag^2
    __shared__ signed char sB[TILE_H * 32];
    float* sS = sX;                                 // smoothed aliases raw tile

    int tx = threadIdx.x, ty = threadIdx.y;
    int tid = ty * 32 + tx;
    int c0 = blockIdx.x * 32;
    int r0 = blockIdx.y * TILE_H;
    int n = blockIdx.z;

    if (blockIdx.x == 0 && blockIdx.y == 0 && n == 0) {
        if (tid == 0) g_acc = 0.0;
        unsigned char* pc = &g_blkchg[0][0][0];
        for (int i = tid; i < NPASS * N_IMG * WW64; i += 256) pc[i] = 0;
    }

    const float* src = x + (size_t)n * HW;

    // load x tile rows r0-10..r0+137, cols c0-12..c0+43
    bool interior = (r0 != 0) && (r0 != H - TILE_H) && (c0 != 0) && (c0 != W - 32);
    if (interior) {
        const float* base = src + (size_t)(r0 - 10) * W + (c0 - 12);
        for (int i = tid; i < T1R * 14; i += 256) {
            int rr = i / 14, q = i - rr * 14;
            *reinterpret_cast<float4*>(sX + rr * XC + q * 4) =
                *reinterpret_cast<const float4*>(base + (size_t)rr * W + q * 4);
        }
    } else {
        for (int i = tid; i < T1R * XC; i += 256) {
            int rr = i / XC, cc = i - rr * XC;
            int gi = reflect_idx(r0 - 10 + rr, H);
            int gj = reflect_idx(c0 - 12 + cc, W);
            sX[i] = src[(size_t)gi * W + gj];
        }
    }
    __syncthreads();

    // row blur: sA[rr][j] = sum_k gw(k) * sX[rr][j+k], j in [0,40)
    for (int i = tid; i < T1R * 10; i += 256) {
        int rr = i / 10, q = i - rr * 10;
        const float* p = sX + rr * XC + q * 4;
        float r[20];
#pragma unroll
        for (int u = 0; u < 5; u++) {
            float4 v = *reinterpret_cast<const float4*>(p + u * 4);
            r[u * 4 + 0] = v.x; r[u * 4 + 1] = v.y; r[u * 4 + 2] = v.z; r[u * 4 + 3] = v.w;
        }
        float a0 = 0.f, a1 = 0.f, a2 = 0.f, a3 = 0.f;
#pragma unroll
        for (int k = 0; k < KLEN; k++) {
            float wk = gw(k);
            a0 += wk * r[k]; a1 += wk * r[k + 1]; a2 += wk * r[k + 2]; a3 += wk * r[k + 3];
        }
        *reinterpret_cast<float4*>(sA + rr * T1C + q * 4) = make_float4(a0, a1, a2, a3);
    }
    __syncthreads();

    // col blur via register streaming (22 loads -> 6 output rows); writes sS (=sX)
    {
        int q = tid % 10;
        int b = tid / 10;
        if (b < 22) {
            const float* p = sA + (6 * b) * T1C + q * 4;
            float acc[6][4];
#pragma unroll
            for (int o = 0; o < 6; o++) { acc[o][0] = acc[o][1] = acc[o][2] = acc[o][3] = 0.f; }
#pragma unroll
            for (int i = 0; i < 22; i++) {
                float4 v = *reinterpret_cast<const float4*>(p + i * T1C);
#pragma unroll
                for (int o = 0; o < 6; o++) {
                    int k = i - o;
                    if (k >= 0 && k < KLEN) {
                        float wk = gw(k);
                        acc[o][0] += wk * v.x; acc[o][1] += wk * v.y;
                        acc[o][2] += wk * v.z; acc[o][3] += wk * v.w;
                    }
                }
            }
            float* d = sS + (6 * b) * T1C + q * 4;
#pragma unroll
            for (int o = 0; o < 6; o++)
                *reinterpret_cast<float4*>(d + o * T1C) =
                    make_float4(acc[o][0], acc[o][1], acc[o][2], acc[o][3]);
        }
    }
    __syncthreads();

    // mag^2 + direction via 3x3 rolling window; writes sA (stride 36)
    {
        int c = tid % 34;
        int b = tid / 34;
        if (b < 7) {
            int rstart = 19 * b;
            const float* p = sS + rstart * T1C + c + 2;
            float a0 = p[0], a1 = p[1], a2 = p[2];
            float b0 = p[T1C], b1 = p[T1C + 1], b2 = p[T1C + 2];
#pragma unroll
            for (int r = 0; r < 19; r++) {
                int rm = rstart + r;
                if (rm < 130) {
                    const float* pr = p + (r + 2) * T1C;
                    float e0 = pr[0], e1 = pr[1], e2 = pr[2];
                    float gx = (a2 - a0) + 2.f * (b2 - b0) + (e2 - e0);
                    float gy = (e0 + 2.f * e1 + e2) - (a0 + 2.f * a1 + a2);
                    sA[rm * MGSTRIDE + c] = gx * gx + gy * gy;
                    if (rm >= 1 && rm <= TILE_H && c >= 1 && c <= 32)
                        sB[(rm - 1) * 32 + (c - 1)] = dir_off(gx, gy);
                    a0 = b0; a1 = b1; a2 = b2;
                    b0 = e0; b1 = e1; b2 = e2;
                }
            }
        }
    }
    __syncthreads();

    if (r0 == 0) { if (tid < 34) sA[tid] = 0.f; }
    if (r0 == H - TILE_H) { if (tid < 34) sA[129 * MGSTRIDE + tid] = 0.f; }
    if (c0 == 0) { for (int i = tid; i < 130; i += 256) sA[i * MGSTRIDE] = 0.f; }
    if (c0 == W - 32) { for (int i = tid; i < 130; i += 256) sA[i * MGSTRIDE + 33] = 0.f; }
    __syncthreads();

    const float TH2 = 0.04f;
    const float TL2 = 0.01f;
    unsigned int* S32 = reinterpret_cast<unsigned int*>(g_strong64);
    unsigned int* W32 = reinterpret_cast<unsigned int*>(g_weak64);
    size_t base = (size_t)n * (HW / 32) + (size_t)blockIdx.x;
#pragma unroll
    for (int s = 0; s < 16; s++) {
        int lr = ty * 16 + s;
        int ci = (lr + 1) * MGSTRIDE + (tx + 1);
        float mc = sA[ci];
        int off = sB[lr * 32 + tx];
        bool keep = (mc >= sA[ci + off]) && (mc >= sA[ci - off]);
        bool strong = keep && (mc > TH2);
        bool weak = keep && (mc > TL2);
        unsigned ws = __ballot_sync(0xffffffffu, strong);
        unsigned ww = __ballot_sync(0xffffffffu, weak);
        if (tx == 0) {
            size_t widx = base + (size_t)(r0 + lr) * WW32;
            S32[widx] = ws;
            W32[widx] = ww;
        }
    }
}

// ---------------- hysteresis: full-height strips, multi-launch ----------------
__device__ __forceinline__ ull rowfill(ull s, ull w) {
    ull up = ((w + s) ^ w) & w;
    ull rs = __brevll(s), rwv = __brevll(w);
    ull dn = __brevll(((rwv + rs) ^ rwv) & rwv);
    return s | up | dn;
}
#define HHX(v) ((v) | ((v) << 1) | ((v) >> 1))

__global__ void k_hyst(int pass) {
    const int bx = blockIdx.x;
    const int n = blockIdx.y;
    const int t = threadIdx.x;

    if (pass > 0) {
        unsigned char l = (bx > 0)        ? g_blkchg[pass - 1][n][bx - 1] : 0;
        unsigned char r = (bx < WW64 - 1) ? g_blkchg[pass - 1][n][bx + 1] : 0;
        if (!(l | r)) return;
    }

    __shared__ ull sTop[256], sBot[256];
    __shared__ unsigned char lbs[1026], rbs[1026];

    ull* S = g_strong64 + (size_t)n * (HW / 64);
    const ull* Wk = g_weak64 + (size_t)n * (HW / 64);

    int gr0 = t * 4;
    ull s[4], w[4];
#pragma unroll
    for (int j = 0; j < 4; j++) {
        size_t off = (size_t)(gr0 + j) * WW64 + bx;
        s[j] = S[off];
        w[j] = Wk[off];
        lbs[gr0 + j + 1] = (bx > 0)        ? (unsigned char)(S[off - 1] >> 63) : 0;
        rbs[gr0 + j + 1] = (bx < WW64 - 1) ? (unsigned char)(S[off + 1] & 1ULL) : 0;
    }
    if (t == 0) { lbs[0] = rbs[0] = lbs[1025] = rbs[1025] = 0; }
    sTop[t] = s[0]; sBot[t] = s[3];
    __syncthreads();

    ull LR[4];
#pragma unroll
    for (int j = 0; j < 4; j++) {
        int i = gr0 + j;
        unsigned l = (unsigned)(lbs[i] | lbs[i + 1] | lbs[i + 2]);
        unsigned r = (unsigned)(rbs[i] | rbs[i + 1] | rbs[i + 2]);
        LR[j] = (ull)(l & 1u) | ((ull)(r & 1u) << 63);
    }

    int any = 0;
    while (true) {
        ull above = (t > 0)   ? sBot[t - 1] : 0ULL;
        ull below = (t < 255) ? sTop[t + 1] : 0ULL;
        ull o0 = s[0], o1 = s[1], o2 = s[2], o3 = s[3];
        s[0] |= (HHX(above) | HHX(s[0]) | HHX(s[1]) | LR[0]) & w[0]; s[0] = rowfill(s[0], w[0]);
        s[1] |= (HHX(s[0])  | HHX(s[1]) | HHX(s[2]) | LR[1]) & w[1]; s[1] = rowfill(s[1], w[1]);
        s[2] |= (HHX(s[1])  | HHX(s[2]) | HHX(s[3]) | LR[2]) & w[2]; s[2] = rowfill(s[2], w[2]);
        s[3] |= (HHX(s[2])  | HHX(s[3]) | HHX(below)| LR[3]) & w[3]; s[3] = rowfill(s[3], w[3]);
        s[2] |= (HHX(s[1]) | HHX(s[2]) | HHX(s[3]) | LR[2]) & w[2]; s[2] = rowfill(s[2], w[2]);
        s[1] |= (HHX(s[0]) | HHX(s[1]) | HHX(s[2]) | LR[1]) & w[1]; s[1] = rowfill(s[1], w[1]);
        s[0] |= (HHX(above)| HHX(s[0]) | HHX(s[1]) | LR[0]) & w[0]; s[0] = rowfill(s[0], w[0]);
        int ch = (s[0] != o0) | (s[1] != o1) | (s[2] != o2) | (s[3] != o3);
        any |= ch;
        __syncthreads();
        sTop[t] = s[0]; sBot[t] = s[3];
        if (!__syncthreads_or(ch)) break;
    }

    if (any) {
#pragma unroll
        for (int j = 0; j < 4; j++) S[(size_t)(gr0 + j) * WW64 + bx] = s[j];
    }
    if (__syncthreads_or(any) && t == 0) g_blkchg[pass][n][bx] = 1;
}

// ---------------- loss: mask register reuse over 4 images/thread ----------------
#define LOSS_BLOCKS 512
__global__ void k_loss(const float* __restrict__ y, const float* __restrict__ mask,
                       float* __restrict__ out) {
    const unsigned int* S32 = reinterpret_cast<const unsigned int*>(g_strong64);
    int gid = blockIdx.x * 256 + threadIdx.x;
    int wp = gid & 32767;
    int grp = gid >> 15;
    const float4* m4 = reinterpret_cast<const float4*>(mask + wp * 32);
    float4 mm[8];
#pragma unroll
    for (int j = 0; j < 8; j++) mm[j] = m4[j];

    float acc = 0.f;
#pragma unroll
    for (int g = 0; g < 4; g++) {
        int n = grp * 4 + g;
        unsigned int bits = S32[n * (HW / 32) + wp];
        const float4* y4 = reinterpret_cast<const float4*>(y + (size_t)n * HW + wp * 32);
#pragma unroll
        for (int j = 0; j < 8; j++) {
            float4 yy = y4[j];
            unsigned int b = bits >> (j * 4);
            float p0 = yy.x * mm[j].x, p1 = yy.y * mm[j].y;
            float p2 = yy.z * mm[j].z, p3 = yy.w * mm[j].w;
            acc += (b & 1u)        ? fabsf(mm[j].x - p0) : p0;
            acc += ((b >> 1) & 1u) ? fabsf(mm[j].y - p1) : p1;
            acc += ((b >> 2) & 1u) ? fabsf(mm[j].z - p2) : p2;
            acc += ((b >> 3) & 1u) ? fabsf(mm[j].w - p3) : p3;
        }
    }
#pragma unroll
    for (int off = 16; off; off >>= 1) acc += __shfl_down_sync(0xffffffffu, acc, off);
    __shared__ float sred[8];
    int lane = threadIdx.x & 31, wid = threadIdx.x >> 5;
    if (lane == 0) sred[wid] = acc;
    __syncthreads();
    if (wid == 0) {
        acc = (lane < 8) ? sred[lane] : 0.f;
#pragma unroll
        for (int off = 4; off; off >>= 1) acc += __shfl_down_sync(0xffffffffu, acc, off);
        if (lane == 0) atomicAdd(&g_acc, (double)acc);
    }
    if (threadIdx.x == 0) {
        __threadfence();
        unsigned int ticket = atomicAdd(&g_ticket, 1u);
        if (ticket == gridDim.x - 1) {
            g_ticket = 0;
            double v = atomicAdd(&g_acc, 0.0);
            out[0] = (float)(v * (1.0 / (double)HW));
        }
    }
}

// ---------------- launch ----------------
extern "C" void kernel_launch(void* const* d_in, const int* in_sizes, int n_in,
                              void* d_out, int out_size) {
    const float* x = nullptr;
    const float* y = nullptr;
    const float* mask = nullptr;
    for (int i = 0; i < n_in; i++) {
        if (in_sizes[i] == HW && mask == nullptr) mask = (const float*)d_in[i];
        else if (x == nullptr) x = (const float*)d_in[i];
        else if (y == nullptr) y = (const float*)d_in[i];
    }

    k_canny<<<dim3(W / 32, H / TILE_H, N_IMG), dim3(32, 8)>>>(x);
    for (int p = 0; p < NPASS; p++)
        k_hyst<<<dim3(WW64, N_IMG), 256>>>(p);
    k_loss<<<LOSS_BLOCKS, 256>>>(y, mask, (float*)d_out);
}

// round 9
// speedup vs baseline: 1.1553x; 1.1553x over previous
#include <cuda_runtime.h>
#include <math.h>

#define N_IMG 16
#define H 1024
#define W 1024
#define HW (H * W)
#define TOT (N_IMG * HW)
#define RAD 8
#define KLEN 17
#define NPASS 3
#define WW64 (W / 64)
#define WW32 (W / 32)

typedef unsigned long long ull;

// gaussian(sigma=2,r=8) weights as compile-time literals
__device__ __forceinline__ float gw(int k) {
    switch (k) {
        case 0: case 16: return 6.6916292e-05f;
        case 1: case 15: return 4.3634888e-04f;
        case 2: case 14: return 2.2159620e-03f;
        case 3: case 13: return 8.7643044e-03f;
        case 4: case 12: return 2.6995958e-02f;
        case 5: case 11: return 6.4759926e-02f;
        case 6: case 10: return 1.2098749e-01f;
        case 7: case 9:  return 1.7603576e-01f;
        default:         return 1.9947465e-01f;
    }
}

// ---------------- scratch ----------------
__device__ float g_t1[TOT];
__device__ ull g_strong64[TOT / 64];
__device__ ull g_weak64[TOT / 64];
__device__ double g_acc;
__device__ unsigned char g_blkchg[NPASS][N_IMG][WW64];
__device__ unsigned int g_ticket;

__device__ __forceinline__ int reflect_idx(int i, int n) {
    if (i < 0) return -i;
    if (i >= n) return 2 * n - 2 - i;
    return i;
}

// ---------------- row blur: grid (H, N), block 256, 4 px/thread ----------------
__global__ void k_rowblur(const float* __restrict__ x) {
    __shared__ __align__(16) float sm[W + 2 * RAD];
    int tid = threadIdx.x;
    if (blockIdx.x == 0 && blockIdx.y == 0) {
        if (tid == 0) g_acc = 0.0;
        unsigned char* pc = &g_blkchg[0][0][0];
        for (int i = tid; i < NPASS * N_IMG * WW64; i += 256) pc[i] = 0;
    }
    int row = blockIdx.x;
    int n = blockIdx.y;
    const float* src = x + ((size_t)n * HW + (size_t)row * W);
    reinterpret_cast<float4*>(sm + RAD)[tid] = reinterpret_cast<const float4*>(src)[tid];
    if (tid < RAD) {
        sm[tid] = src[RAD - tid];
        sm[W + RAD + tid] = src[W - 2 - tid];
    }
    __syncthreads();
    int j = tid * 4;
    float r[20];
#pragma unroll
    for (int q = 0; q < 5; q++) {
        float4 v = *reinterpret_cast<const float4*>(sm + j + q * 4);
        r[q * 4 + 0] = v.x; r[q * 4 + 1] = v.y; r[q * 4 + 2] = v.z; r[q * 4 + 3] = v.w;
    }
    float a0 = 0.f, a1 = 0.f, a2 = 0.f, a3 = 0.f;
#pragma unroll
    for (int k = 0; k < KLEN; k++) {
        float wk = gw(k);
        a0 += wk * r[k]; a1 += wk * r[k + 1]; a2 += wk * r[k + 2]; a3 += wk * r[k + 3];
    }
    float* dst = g_t1 + ((size_t)n * HW + (size_t)row * W);
    reinterpret_cast<float4*>(dst)[tid] = make_float4(a0, a1, a2, a3);
}

// ---------------- fused colblur + sobel(mag^2) + NMS + thresholds ----------------
#define TILE_H 128
#define T1R 148
#define T1C 40
#define SSR 132
#define MGSTRIDE 36

__device__ __forceinline__ signed char dir_off(float u, float v) {
    if (v < 0.f || (v == 0.f && u < 0.f)) { u = -u; v = -v; }
    const float c1 = 0.41421356237309503f;
    const float c2 = 2.414213562373095f;
    if (u > 0.f) {
        if (v < c1 * u)      return 1;
        else if (v < c2 * u) return -(MGSTRIDE - 1);
        else                 return -MGSTRIDE;
    } else if (u < 0.f) {
        float t = -u;
        if (v <= c1 * t)     return 1;
        else if (v > c2 * t) return -MGSTRIDE;
        else                 return -(MGSTRIDE + 1);
    }
    return -MGSTRIDE;
}

__global__ void k_colsobel() {
    __shared__ __align__(16) float sA[T1R * T1C];   // raw; later mag^2 (stride 36)
    __shared__ __align__(16) float sS[SSR * T1C];   // smoothed
    __shared__ signed char sB[TILE_H * 32];
    int tx = threadIdx.x, ty = threadIdx.y;
    int tid = ty * 32 + tx;
    int c0 = blockIdx.x * 32;
    int r0 = blockIdx.y * TILE_H;
    int n = blockIdx.z;
    const float* src = g_t1 + (size_t)n * HW;

    bool interior = (r0 != 0) && (r0 != H - TILE_H) && (c0 != 0) && (c0 != W - 32);
    if (interior) {
        const float* base = src + (size_t)(r0 - 10) * W + (c0 - 4);
        for (int i = tid; i < T1R * 10; i += 256) {
            int rr = i / 10, q = i - rr * 10;
            *reinterpret_cast<float4*>(sA + rr * T1C + q * 4) =
                *reinterpret_cast<const float4*>(base + (size_t)rr * W + q * 4);
        }
    } else {
        for (int i = tid; i < T1R * T1C; i += 256) {
            int rr = i / T1C, cc = i - rr * T1C;
            int gi = reflect_idx(r0 - 10 + rr, H);
            int gj = reflect_idx(c0 - 4 + cc, W);
            sA[i] = src[(size_t)gi * W + gj];
        }
    }
    __syncthreads();

    // phase A: vertical blur via register streaming (22 loads -> 6 output rows)
    {
        int q = tid % 10;
        int b = tid / 10;
        if (b < 22) {
            const float* p = sA + (6 * b) * T1C + q * 4;
            float acc[6][4];
#pragma unroll
            for (int o = 0; o < 6; o++) { acc[o][0] = acc[o][1] = acc[o][2] = acc[o][3] = 0.f; }
#pragma unroll
            for (int i = 0; i < 22; i++) {
                float4 v = *reinterpret_cast<const float4*>(p + i * T1C);
#pragma unroll
                for (int o = 0; o < 6; o++) {
                    int k = i - o;
                    if (k >= 0 && k < KLEN) {
                        float wk = gw(k);
                        acc[o][0] += wk * v.x; acc[o][1] += wk * v.y;
                        acc[o][2] += wk * v.z; acc[o][3] += wk * v.w;
                    }
                }
            }
            float* d = sS + (6 * b) * T1C + q * 4;
#pragma unroll
            for (int o = 0; o < 6; o++)
                *reinterpret_cast<float4*>(d + o * T1C) =
                    make_float4(acc[o][0], acc[o][1], acc[o][2], acc[o][3]);
        }
    }
    __syncthreads();

    // phase B: mag^2 + direction via 3x3 rolling window (3 loads/px)
    {
        int c = tid % 34;
        int b = tid / 34;
        if (b < 7) {
            int rstart = 19 * b;
            const float* p = sS + rstart * T1C + c + 2;
            float a0 = p[0], a1 = p[1], a2 = p[2];
            float b0 = p[T1C], b1 = p[T1C + 1], b2 = p[T1C + 2];
#pragma unroll
            for (int r = 0; r < 19; r++) {
                int rm = rstart + r;
                if (rm < 130) {
                    const float* pr = p + (r + 2) * T1C;
                    float e0 = pr[0], e1 = pr[1], e2 = pr[2];
                    float gx = (a2 - a0) + 2.f * (b2 - b0) + (e2 - e0);
                    float gy = (e0 + 2.f * e1 + e2) - (a0 + 2.f * a1 + a2);
                    sA[rm * MGSTRIDE + c] = gx * gx + gy * gy;
                    if (rm >= 1 && rm <= TILE_H && c >= 1 && c <= 32)
                        sB[(rm - 1) * 32 + (c - 1)] = dir_off(gx, gy);
                    a0 = b0; a1 = b1; a2 = b2;
                    b0 = e0; b1 = e1; b2 = e2;
                }
            }
        }
    }
    __syncthreads();

    if (r0 == 0) { if (tid < 34) sA[tid] = 0.f; }
    if (r0 == H - TILE_H) { if (tid < 34) sA[129 * MGSTRIDE + tid] = 0.f; }
    if (c0 == 0) { for (int i = tid; i < 130; i += 256) sA[i * MGSTRIDE] = 0.f; }
    if (c0 == W - 32) { for (int i = tid; i < 130; i += 256) sA[i * MGSTRIDE + 33] = 0.f; }
    __syncthreads();

    const float TH2 = 0.04f;
    const float TL2 = 0.01f;
    unsigned int* S32 = reinterpret_cast<unsigned int*>(g_strong64);
    unsigned int* W32 = reinterpret_cast<unsigned int*>(g_weak64);
    size_t base = (size_t)n * (HW / 32) + (size_t)blockIdx.x;
#pragma unroll
    for (int s = 0; s < 16; s++) {
        int lr = ty * 16 + s;
        int ci = (lr + 1) * MGSTRIDE + (tx + 1);
        float mc = sA[ci];
        int off = sB[lr * 32 + tx];
        bool keep = (mc >= sA[ci + off]) && (mc >= sA[ci - off]);
        bool strong = keep && (mc > TH2);
        bool weak = keep && (mc > TL2);
        unsigned ws = __ballot_sync(0xffffffffu, strong);
        unsigned ww = __ballot_sync(0xffffffffu, weak);
        if (tx == 0) {
            size_t widx = base + (size_t)(r0 + lr) * WW32;
            S32[widx] = ws;
            W32[widx] = ww;
        }
    }
}

// ---------------- hysteresis: full-height strips, double-buffered (1 BAR/iter) ----
__device__ __forceinline__ ull rowfill(ull s, ull w) {
    ull up = ((w + s) ^ w) & w;
    ull rs = __brevll(s), rwv = __brevll(w);
    ull dn = __brevll(((rwv + rs) ^ rwv) & rwv);
    return s | up | dn;
}
#define HHX(v) ((v) | ((v) << 1) | ((v) >> 1))

__global__ void k_hyst(int pass) {
    const int bx = blockIdx.x;
    const int n = blockIdx.y;
    const int t = threadIdx.x;

    if (pass > 0) {
        unsigned char l = (bx > 0)        ? g_blkchg[pass - 1][n][bx - 1] : 0;
        unsigned char r = (bx < WW64 - 1) ? g_blkchg[pass - 1][n][bx + 1] : 0;
        if (!(l | r)) return;
    }

    __shared__ ull sTop[2][256], sBot[2][256];
    __shared__ unsigned char lbs[1026], rbs[1026];

    ull* S = g_strong64 + (size_t)n * (HW / 64);
    const ull* Wk = g_weak64 + (size_t)n * (HW / 64);

    int gr0 = t * 4;
    ull s[4], w[4];
#pragma unroll
    for (int j = 0; j < 4; j++) {
        size_t off = (size_t)(gr0 + j) * WW64 + bx;
        s[j] = S[off];
        w[j] = Wk[off];
        lbs[gr0 + j + 1] = (bx > 0)        ? (unsigned char)(S[off - 1] >> 63) : 0;
        rbs[gr0 + j + 1] = (bx < WW64 - 1) ? (unsigned char)(S[off + 1] & 1ULL) : 0;
    }
    if (t == 0) { lbs[0] = rbs[0] = lbs[1025] = rbs[1025] = 0; }
    sTop[0][t] = s[0]; sBot[0][t] = s[3];
    __syncthreads();

    ull LR[4];
#pragma unroll
    for (int j = 0; j < 4; j++) {
        int i = gr0 + j;
        unsigned l = (unsigned)(lbs[i] | lbs[i + 1] | lbs[i + 2]);
        unsigned r = (unsigned)(rbs[i] | rbs[i + 1] | rbs[i + 2]);
        LR[j] = (ull)(l & 1u) | ((ull)(r & 1u) << 63);
    }

    int any = 0;
    int pb = 0;
    while (true) {
        ull above = (t > 0)   ? sBot[pb][t - 1] : 0ULL;
        ull below = (t < 255) ? sTop[pb][t + 1] : 0ULL;
        ull o0 = s[0], o1 = s[1], o2 = s[2], o3 = s[3];
        s[0] |= (HHX(above) | HHX(s[0]) | HHX(s[1]) | LR[0]) & w[0]; s[0] = rowfill(s[0], w[0]);
        s[1] |= (HHX(s[0])  | HHX(s[1]) | HHX(s[2]) | LR[1]) & w[1]; s[1] = rowfill(s[1], w[1]);
        s[2] |= (HHX(s[1])  | HHX(s[2]) | HHX(s[3]) | LR[2]) & w[2]; s[2] = rowfill(s[2], w[2]);
        s[3] |= (HHX(s[2])  | HHX(s[3]) | HHX(below)| LR[3]) & w[3]; s[3] = rowfill(s[3], w[3]);
        s[2] |= (HHX(s[1]) | HHX(s[2]) | HHX(s[3]) | LR[2]) & w[2]; s[2] = rowfill(s[2], w[2]);
        s[1] |= (HHX(s[0]) | HHX(s[1]) | HHX(s[2]) | LR[1]) & w[1]; s[1] = rowfill(s[1], w[1]);
        s[0] |= (HHX(above)| HHX(s[0]) | HHX(s[1]) | LR[0]) & w[0]; s[0] = rowfill(s[0], w[0]);
        int ch = (s[0] != o0) | (s[1] != o1) | (s[2] != o2) | (s[3] != o3);
        any |= ch;
        sTop[pb ^ 1][t] = s[0]; sBot[pb ^ 1][t] = s[3];
        pb ^= 1;
        if (!__syncthreads_or(ch)) break;   // single barrier per iteration
    }

    if (any) {
#pragma unroll
        for (int j = 0; j < 4; j++) S[(size_t)(gr0 + j) * WW64 + bx] = s[j];
    }
    if (__syncthreads_or(any) && t == 0) g_blkchg[pass][n][bx] = 1;
}

// ---------------- loss: mask register reuse over 4 images/thread ----------------
#define LOSS_BLOCKS 512
__global__ void k_loss(const float* __restrict__ y, const float* __restrict__ mask,
                       float* __restrict__ out) {
    const unsigned int* S32 = reinterpret_cast<const unsigned int*>(g_strong64);
    int gid = blockIdx.x * 256 + threadIdx.x;
    int wp = gid & 32767;
    int grp = gid >> 15;
    const float4* m4 = reinterpret_cast<const float4*>(mask + wp * 32);
    float4 mm[8];
#pragma unroll
    for (int j = 0; j < 8; j++) mm[j] = m4[j];

    float acc = 0.f;
#pragma unroll
    for (int g = 0; g < 4; g++) {
        int n = grp * 4 + g;
        unsigned int bits = S32[n * (HW / 32) + wp];
        const float4* y4 = reinterpret_cast<const float4*>(y + (size_t)n * HW + wp * 32);
#pragma unroll
        for (int j = 0; j < 8; j++) {
            float4 yy = y4[j];
            unsigned int b = bits >> (j * 4);
            float p0 = yy.x * mm[j].x, p1 = yy.y * mm[j].y;
            float p2 = yy.z * mm[j].z, p3 = yy.w * mm[j].w;
            acc += (b & 1u)        ? fabsf(mm[j].x - p0) : p0;
            acc += ((b >> 1) & 1u) ? fabsf(mm[j].y - p1) : p1;
            acc += ((b >> 2) & 1u) ? fabsf(mm[j].z - p2) : p2;
            acc += ((b >> 3) & 1u) ? fabsf(mm[j].w - p3) : p3;
        }
    }
#pragma unroll
    for (int off = 16; off; off >>= 1) acc += __shfl_down_sync(0xffffffffu, acc, off);
    __shared__ float sred[8];
    int lane = threadIdx.x & 31, wid = threadIdx.x >> 5;
    if (lane == 0) sred[wid] = acc;
    __syncthreads();
    if (wid == 0) {
        acc = (lane < 8) ? sred[lane] : 0.f;
#pragma unroll
        for (int off = 4; off; off >>= 1) acc += __shfl_down_sync(0xffffffffu, acc, off);
        if (lane == 0) atomicAdd(&g_acc, (double)acc);
    }
    if (threadIdx.x == 0) {
        __threadfence();
        unsigned int ticket = atomicAdd(&g_ticket, 1u);
        if (ticket == gridDim.x - 1) {
            g_ticket = 0;
            double v = atomicAdd(&g_acc, 0.0);
            out[0] = (float)(v * (1.0 / (double)HW));
        }
    }
}

// ---------------- launch ----------------
extern "C" void kernel_launch(void* const* d_in, const int* in_sizes, int n_in,
                              void* d_out, int out_size) {
    const float* x = nullptr;
    const float* y = nullptr;
    const float* mask = nullptr;
    for (int i = 0; i < n_in; i++) {
        if (in_sizes[i] == HW && mask == nullptr) mask = (const float*)d_in[i];
        else if (x == nullptr) x = (const float*)d_in[i];
        else if (y == nullptr) y = (const float*)d_in[i];
    }

    k_rowblur<<<dim3(H, N_IMG), 256>>>(x);
    k_colsobel<<<dim3(W / 32, H / TILE_H, N_IMG), dim3(32, 8)>>>();
    for (int p = 0; p < NPASS; p++)
        k_hyst<<<dim3(WW64, N_IMG), 256>>>(p);
    k_loss<<<LOSS_BLOCKS, 256>>>(y, mask, (float*)d_out);
}

// round 10
// speedup vs baseline: 1.2404x; 1.0737x over previous
#include <cuda_runtime.h>
#include <math.h>

#define N_IMG 16
#define H 1024
#define W 1024
#define HW (H * W)
#define TOT (N_IMG * HW)
#define RAD 8
#define KLEN 17
#define NPASS 2
#define WW64 (W / 64)
#define WW32 (W / 32)

typedef unsigned long long ull;

// gaussian(sigma=2,r=8) weights as compile-time literals
__device__ __forceinline__ float gw(int k) {
    switch (k) {
        case 0: case 16: return 6.6916292e-05f;
        case 1: case 15: return 4.3634888e-04f;
        case 2: case 14: return 2.2159620e-03f;
        case 3: case 13: return 8.7643044e-03f;
        case 4: case 12: return 2.6995958e-02f;
        case 5: case 11: return 6.4759926e-02f;
        case 6: case 10: return 1.2098749e-01f;
        case 7: case 9:  return 1.7603576e-01f;
        default:         return 1.9947465e-01f;
    }
}

// ---------------- scratch ----------------
__device__ float g_t1[TOT];
__device__ ull g_strong64[TOT / 64];
__device__ ull g_weak64[TOT / 64];
__device__ double g_acc;
__device__ unsigned char g_blkchg[NPASS][N_IMG][WW64];
__device__ unsigned int g_ticket;

__device__ __forceinline__ int reflect_idx(int i, int n) {
    if (i < 0) return -i;
    if (i >= n) return 2 * n - 2 - i;
    return i;
}

// ---------------- row blur: grid (H/4, N), block 256, 4 rows x 4 px/thread -------
#define RB_ROWS 4
__global__ void k_rowblur(const float* __restrict__ x) {
    __shared__ __align__(16) float sm[RB_ROWS][W + 2 * RAD];
    int tid = threadIdx.x;
    if (blockIdx.x == 0 && blockIdx.y == 0) {
        if (tid == 0) g_acc = 0.0;
        unsigned char* pc = &g_blkchg[0][0][0];
        for (int i = tid; i < NPASS * N_IMG * WW64; i += 256) pc[i] = 0;
    }
    int r0 = blockIdx.x * RB_ROWS;
    int n = blockIdx.y;
#pragma unroll
    for (int rr = 0; rr < RB_ROWS; rr++) {
        const float* src = x + ((size_t)n * HW + (size_t)(r0 + rr) * W);
        reinterpret_cast<float4*>(sm[rr] + RAD)[tid] = reinterpret_cast<const float4*>(src)[tid];
        if (tid < RAD) {
            sm[rr][tid] = src[RAD - tid];
            sm[rr][W + RAD + tid] = src[W - 2 - tid];
        }
    }
    __syncthreads();
    int j = tid * 4;
#pragma unroll
    for (int rr = 0; rr < RB_ROWS; rr++) {
        float r[20];
#pragma unroll
        for (int q = 0; q < 5; q++) {
            float4 v = *reinterpret_cast<const float4*>(sm[rr] + j + q * 4);
            r[q * 4 + 0] = v.x; r[q * 4 + 1] = v.y; r[q * 4 + 2] = v.z; r[q * 4 + 3] = v.w;
        }
        float a0 = 0.f, a1 = 0.f, a2 = 0.f, a3 = 0.f;
#pragma unroll
        for (int k = 0; k < KLEN; k++) {
            float wk = gw(k);
            a0 += wk * r[k]; a1 += wk * r[k + 1]; a2 += wk * r[k + 2]; a3 += wk * r[k + 3];
        }
        float* dst = g_t1 + ((size_t)n * HW + (size_t)(r0 + rr) * W);
        reinterpret_cast<float4*>(dst)[tid] = make_float4(a0, a1, a2, a3);
    }
}

// ---------------- fused colblur + sobel(mag^2) + NMS + thresholds ----------------
#define TILE_H 128
#define T1R 148
#define T1C 40
#define SSR 132
#define MGSTRIDE 36

__device__ __forceinline__ signed char dir_off(float u, float v) {
    if (v < 0.f || (v == 0.f && u < 0.f)) { u = -u; v = -v; }
    const float c1 = 0.41421356237309503f;
    const float c2 = 2.414213562373095f;
    if (u > 0.f) {
        if (v < c1 * u)      return 1;
        else if (v < c2 * u) return -(MGSTRIDE - 1);
        else                 return -MGSTRIDE;
    } else if (u < 0.f) {
        float t = -u;
        if (v <= c1 * t)     return 1;
        else if (v > c2 * t) return -MGSTRIDE;
        else                 return -(MGSTRIDE + 1);
    }
    return -MGSTRIDE;
}

__global__ void k_colsobel() {
    __shared__ __align__(16) float sA[T1R * T1C];   // raw; later mag^2 (stride 36)
    __shared__ __align__(16) float sS[SSR * T1C];   // smoothed
    __shared__ signed char sB[TILE_H * 32];
    int tx = threadIdx.x, ty = threadIdx.y;
    int tid = ty * 32 + tx;
    int c0 = blockIdx.x * 32;
    int r0 = blockIdx.y * TILE_H;
    int n = blockIdx.z;
    const float* src = g_t1 + (size_t)n * HW;

    bool interior = (r0 != 0) && (r0 != H - TILE_H) && (c0 != 0) && (c0 != W - 32);
    if (interior) {
        const float* base = src + (size_t)(r0 - 10) * W + (c0 - 4);
        for (int i = tid; i < T1R * 10; i += 256) {
            int rr = i / 10, q = i - rr * 10;
            *reinterpret_cast<float4*>(sA + rr * T1C + q * 4) =
                *reinterpret_cast<const float4*>(base + (size_t)rr * W + q * 4);
        }
    } else {
        for (int i = tid; i < T1R * T1C; i += 256) {
            int rr = i / T1C, cc = i - rr * T1C;
            int gi = reflect_idx(r0 - 10 + rr, H);
            int gj = reflect_idx(c0 - 4 + cc, W);
            sA[i] = src[(size_t)gi * W + gj];
        }
    }
    __syncthreads();

    // phase A: vertical blur via register streaming (22 loads -> 6 output rows)
    {
        int q = tid % 10;
        int b = tid / 10;
        if (b < 22) {
            const float* p = sA + (6 * b) * T1C + q * 4;
            float acc[6][4];
#pragma unroll
            for (int o = 0; o < 6; o++) { acc[o][0] = acc[o][1] = acc[o][2] = acc[o][3] = 0.f; }
#pragma unroll
            for (int i = 0; i < 22; i++) {
                float4 v = *reinterpret_cast<const float4*>(p + i * T1C);
#pragma unroll
                for (int o = 0; o < 6; o++) {
                    int k = i - o;
                    if (k >= 0 && k < KLEN) {
                        float wk = gw(k);
                        acc[o][0] += wk * v.x; acc[o][1] += wk * v.y;
                        acc[o][2] += wk * v.z; acc[o][3] += wk * v.w;
                    }
                }
            }
            float* d = sS + (6 * b) * T1C + q * 4;
#pragma unroll
            for (int o = 0; o < 6; o++)
                *reinterpret_cast<float4*>(d + o * T1C) =
                    make_float4(acc[o][0], acc[o][1], acc[o][2], acc[o][3]);
        }
    }
    __syncthreads();

    // phase B: mag^2 + direction via 3x3 rolling window (3 loads/px)
    {
        int c = tid % 34;
        int b = tid / 34;
        if (b < 7) {
            int rstart = 19 * b;
            const float* p = sS + rstart * T1C + c + 2;
            float a0 = p[0], a1 = p[1], a2 = p[2];
            float b0 = p[T1C], b1 = p[T1C + 1], b2 = p[T1C + 2];
#pragma unroll
            for (int r = 0; r < 19; r++) {
                int rm = rstart + r;
                if (rm < 130) {
                    const float* pr = p + (r + 2) * T1C;
                    float e0 = pr[0], e1 = pr[1], e2 = pr[2];
                    float gx = (a2 - a0) + 2.f * (b2 - b0) + (e2 - e0);
                    float gy = (e0 + 2.f * e1 + e2) - (a0 + 2.f * a1 + a2);
                    sA[rm * MGSTRIDE + c] = gx * gx + gy * gy;
                    if (rm >= 1 && rm <= TILE_H && c >= 1 && c <= 32)
                        sB[(rm - 1) * 32 + (c - 1)] = dir_off(gx, gy);
                    a0 = b0; a1 = b1; a2 = b2;
                    b0 = e0; b1 = e1; b2 = e2;
                }
            }
        }
    }
    __syncthreads();

    // border zeroing only on border tiles (block-uniform predicate)
    if (!interior) {
        if (r0 == 0 && tid < 34) sA[tid] = 0.f;
        if (r0 == H - TILE_H && tid < 34) sA[129 * MGSTRIDE + tid] = 0.f;
        if (c0 == 0) { for (int i = tid; i < 130; i += 256) sA[i * MGSTRIDE] = 0.f; }
        if (c0 == W - 32) { for (int i = tid; i < 130; i += 256) sA[i * MGSTRIDE + 33] = 0.f; }
        __syncthreads();
    }

    const float TH2 = 0.04f;
    const float TL2 = 0.01f;
    unsigned int* S32 = reinterpret_cast<unsigned int*>(g_strong64);
    unsigned int* W32 = reinterpret_cast<unsigned int*>(g_weak64);
    size_t base = (size_t)n * (HW / 32) + (size_t)blockIdx.x;
#pragma unroll
    for (int s = 0; s < 16; s++) {
        int lr = ty * 16 + s;
        int ci = (lr + 1) * MGSTRIDE + (tx + 1);
        float mc = sA[ci];
        int off = sB[lr * 32 + tx];
        bool keep = (mc >= sA[ci + off]) && (mc >= sA[ci - off]);
        bool strong = keep && (mc > TH2);
        bool weak = keep && (mc > TL2);
        unsigned ws = __ballot_sync(0xffffffffu, strong);
        unsigned ww = __ballot_sync(0xffffffffu, weak);
        if (tx == 0) {
            size_t widx = base + (size_t)(r0 + lr) * WW32;
            S32[widx] = ws;
            W32[widx] = ww;
        }
    }
}

// ---------------- hysteresis: full-height strips, double-buffered (1 BAR/iter) ----
__device__ __forceinline__ ull rowfill(ull s, ull w) {
    ull up = ((w + s) ^ w) & w;
    ull rs = __brevll(s), rwv = __brevll(w);
    ull dn = __brevll(((rwv + rs) ^ rwv) & rwv);
    return s | up | dn;
}
#define HHX(v) ((v) | ((v) << 1) | ((v) >> 1))

__global__ void k_hyst(int pass) {
    const int bx = blockIdx.x;
    const int n = blockIdx.y;
    const int t = threadIdx.x;

    if (pass > 0) {
        unsigned char l = (bx > 0)        ? g_blkchg[pass - 1][n][bx - 1] : 0;
        unsigned char r = (bx < WW64 - 1) ? g_blkchg[pass - 1][n][bx + 1] : 0;
        if (!(l | r)) return;
    }

    __shared__ ull sTop[2][256], sBot[2][256];
    __shared__ unsigned char lbs[1026], rbs[1026];

    ull* S = g_strong64 + (size_t)n * (HW / 64);
    const ull* Wk = g_weak64 + (size_t)n * (HW / 64);

    int gr0 = t * 4;
    ull s[4], w[4];
#pragma unroll
    for (int j = 0; j < 4; j++) {
        size_t off = (size_t)(gr0 + j) * WW64 + bx;
        s[j] = S[off];
        w[j] = Wk[off];
        lbs[gr0 + j + 1] = (bx > 0)        ? (unsigned char)(S[off - 1] >> 63) : 0;
        rbs[gr0 + j + 1] = (bx < WW64 - 1) ? (unsigned char)(S[off + 1] & 1ULL) : 0;
    }
    if (t == 0) { lbs[0] = rbs[0] = lbs[1025] = rbs[1025] = 0; }
    sTop[0][t] = s[0]; sBot[0][t] = s[3];
    __syncthreads();

    ull LR[4];
#pragma unroll
    for (int j = 0; j < 4; j++) {
        int i = gr0 + j;
        unsigned l = (unsigned)(lbs[i] | lbs[i + 1] | lbs[i + 2]);
        unsigned r = (unsigned)(rbs[i] | rbs[i + 1] | rbs[i + 2]);
        LR[j] = (ull)(l & 1u) | ((ull)(r & 1u) << 63);
    }

    int any = 0;
    int pb = 0;
    while (true) {
        ull above = (t > 0)   ? sBot[pb][t - 1] : 0ULL;
        ull below = (t < 255) ? sTop[pb][t + 1] : 0ULL;
        ull o0 = s[0], o1 = s[1], o2 = s[2], o3 = s[3];
        s[0] |= (HHX(above) | HHX(s[0]) | HHX(s[1]) | LR[0]) & w[0]; s[0] = rowfill(s[0], w[0]);
        s[1] |= (HHX(s[0])  | HHX(s[1]) | HHX(s[2]) | LR[1]) & w[1]; s[1] = rowfill(s[1], w[1]);
        s[2] |= (HHX(s[1])  | HHX(s[2]) | HHX(s[3]) | LR[2]) & w[2]; s[2] = rowfill(s[2], w[2]);
        s[3] |= (HHX(s[2])  | HHX(s[3]) | HHX(below)| LR[3]) & w[3]; s[3] = rowfill(s[3], w[3]);
        s[2] |= (HHX(s[1]) | HHX(s[2]) | HHX(s[3]) | LR[2]) & w[2]; s[2] = rowfill(s[2], w[2]);
        s[1] |= (HHX(s[0]) | HHX(s[1]) | HHX(s[2]) | LR[1]) & w[1]; s[1] = rowfill(s[1], w[1]);
        s[0] |= (HHX(above)| HHX(s[0]) | HHX(s[1]) | LR[0]) & w[0]; s[0] = rowfill(s[0], w[0]);
        int ch = (s[0] != o0) | (s[1] != o1) | (s[2] != o2) | (s[3] != o3);
        any |= ch;
        sTop[pb ^ 1][t] = s[0]; sBot[pb ^ 1][t] = s[3];
        pb ^= 1;
        if (!__syncthreads_or(ch)) break;
    }

    if (any) {
#pragma unroll
        for (int j = 0; j < 4; j++) S[(size_t)(gr0 + j) * WW64 + bx] = s[j];
    }
    if (__syncthreads_or(any) && t == 0) g_blkchg[pass][n][bx] = 1;
}

// ---------------- loss: mask register reuse over 4 images/thread ----------------
#define LOSS_BLOCKS 512
__global__ void k_loss(const float* __restrict__ y, const float* __restrict__ mask,
                       float* __restrict__ out) {
    const unsigned int* S32 = reinterpret_cast<const unsigned int*>(g_strong64);
    int gid = blockIdx.x * 256 + threadIdx.x;
    int wp = gid & 32767;
    int grp = gid >> 15;
    const float4* m4 = reinterpret_cast<const float4*>(mask + wp * 32);
    float4 mm[8];
#pragma unroll
    for (int j = 0; j < 8; j++) mm[j] = m4[j];

    float acc = 0.f;
#pragma unroll
    for (int g = 0; g < 4; g++) {
        int n = grp * 4 + g;
        unsigned int bits = S32[n * (HW / 32) + wp];
        const float4* y4 = reinterpret_cast<const float4*>(y + (size_t)n * HW + wp * 32);
#pragma unroll
        for (int j = 0; j < 8; j++) {
            float4 yy = y4[j];
            unsigned int b = bits >> (j * 4);
            float p0 = yy.x * mm[j].x, p1 = yy.y * mm[j].y;
            float p2 = yy.z * mm[j].z, p3 = yy.w * mm[j].w;
            acc += (b & 1u)        ? fabsf(mm[j].x - p0) : p0;
            acc += ((b >> 1) & 1u) ? fabsf(mm[j].y - p1) : p1;
            acc += ((b >> 2) & 1u) ? fabsf(mm[j].z - p2) : p2;
            acc += ((b >> 3) & 1u) ? fabsf(mm[j].w - p3) : p3;
        }
    }
#pragma unroll
    for (int off = 16; off; off >>= 1) acc += __shfl_down_sync(0xffffffffu, acc, off);
    __shared__ float sred[8];
    int lane = threadIdx.x & 31, wid = threadIdx.x >> 5;
    if (lane == 0) sred[wid] = acc;
    __syncthreads();
    if (wid == 0) {
        acc = (lane < 8) ? sred[lane] : 0.f;
#pragma unroll
        for (int off = 4; off; off >>= 1) acc += __shfl_down_sync(0xffffffffu, acc, off);
        if (lane == 0) atomicAdd(&g_acc, (double)acc);
    }
    if (threadIdx.x == 0) {
        __threadfence();
        unsigned int ticket = atomicAdd(&g_ticket, 1u);
        if (ticket == gridDim.x - 1) {
            g_ticket = 0;
            double v = atomicAdd(&g_acc, 0.0);
            out[0] = (float)(v * (1.0 / (double)HW));
        }
    }
}

// ---------------- launch ----------------
extern "C" void kernel_launch(void* const* d_in, const int* in_sizes, int n_in,
                              void* d_out, int out_size) {
    const float* x = nullptr;
    const float* y = nullptr;
    const float* mask = nullptr;
    for (int i = 0; i < n_in; i++) {
        if (in_sizes[i] == HW && mask == nullptr) mask = (const float*)d_in[i];
        else if (x == nullptr) x = (const float*)d_in[i];
        else if (y == nullptr) y = (const float*)d_in[i];
    }

    k_rowblur<<<dim3(H / RB_ROWS, N_IMG), 256>>>(x);
    k_colsobel<<<dim3(W / 32, H / TILE_H, N_IMG), dim3(32, 8)>>>();
    for (int p = 0; p < NPASS; p++)
        k_hyst<<<dim3(WW64, N_IMG), 256>>>(p);
    k_loss<<<LOSS_BLOCKS, 256>>>(y, mask, (float*)d_out);
}

// round 11
// speedup vs baseline: 1.3231x; 1.0667x over previous
#include <cuda_runtime.h>
#include <math.h>

#define N_IMG 16
#define H 1024
#define W 1024
#define HW (H * W)
#define TOT (N_IMG * HW)
#define RAD 8
#define KLEN 17
#define WW64 (W / 64)
#define WW32 (W / 32)

typedef unsigned long long ull;

// gaussian(sigma=2,r=8) weights as compile-time literals
__device__ __forceinline__ float gw(int k) {
    switch (k) {
        case 0: case 16: return 6.6916292e-05f;
        case 1: case 15: return 4.3634888e-04f;
        case 2: case 14: return 2.2159620e-03f;
        case 3: case 13: return 8.7643044e-03f;
        case 4: case 12: return 2.6995958e-02f;
        case 5: case 11: return 6.4759926e-02f;
        case 6: case 10: return 1.2098749e-01f;
        case 7: case 9:  return 1.7603576e-01f;
        default:         return 1.9947465e-01f;
    }
}

// ---------------- scratch ----------------
__device__ float g_t1[TOT];
__device__ ull g_strong64[TOT / 64];
__device__ ull g_weak64[TOT / 64];
__device__ double g_acc;
__device__ unsigned int g_ticket;

__device__ __forceinline__ int reflect_idx(int i, int n) {
    if (i < 0) return -i;
    if (i >= n) return 2 * n - 2 - i;
    return i;
}

// ---------------- row blur: grid (H/4, N), block 256, 4 rows x 4 px/thread -------
#define RB_ROWS 4
__global__ void k_rowblur(const float* __restrict__ x) {
    __shared__ __align__(16) float sm[RB_ROWS][W + 2 * RAD];
    int tid = threadIdx.x;
    if (blockIdx.x == 0 && blockIdx.y == 0 && tid == 0) g_acc = 0.0;
    int r0 = blockIdx.x * RB_ROWS;
    int n = blockIdx.y;
#pragma unroll
    for (int rr = 0; rr < RB_ROWS; rr++) {
        const float* src = x + ((size_t)n * HW + (size_t)(r0 + rr) * W);
        reinterpret_cast<float4*>(sm[rr] + RAD)[tid] = reinterpret_cast<const float4*>(src)[tid];
        if (tid < RAD) {
            sm[rr][tid] = src[RAD - tid];
            sm[rr][W + RAD + tid] = src[W - 2 - tid];
        }
    }
    __syncthreads();
    int j = tid * 4;
#pragma unroll
    for (int rr = 0; rr < RB_ROWS; rr++) {
        float r[20];
#pragma unroll
        for (int q = 0; q < 5; q++) {
            float4 v = *reinterpret_cast<const float4*>(sm[rr] + j + q * 4);
            r[q * 4 + 0] = v.x; r[q * 4 + 1] = v.y; r[q * 4 + 2] = v.z; r[q * 4 + 3] = v.w;
        }
        float a0 = 0.f, a1 = 0.f, a2 = 0.f, a3 = 0.f;
#pragma unroll
        for (int k = 0; k < KLEN; k++) {
            float wk = gw(k);
            a0 += wk * r[k]; a1 += wk * r[k + 1]; a2 += wk * r[k + 2]; a3 += wk * r[k + 3];
        }
        float* dst = g_t1 + ((size_t)n * HW + (size_t)(r0 + rr) * W);
        reinterpret_cast<float4*>(dst)[tid] = make_float4(a0, a1, a2, a3);
    }
}

// ---------------- fused colblur + sobel(mag^2) + NMS + thresholds ----------------
#define TILE_H 128
#define T1R 148
#define T1C 40
#define SSR 132
#define MGSTRIDE 36

__device__ __forceinline__ signed char dir_off(float u, float v) {
    if (v < 0.f || (v == 0.f && u < 0.f)) { u = -u; v = -v; }
    const float c1 = 0.41421356237309503f;
    const float c2 = 2.414213562373095f;
    if (u > 0.f) {
        if (v < c1 * u)      return 1;
        else if (v < c2 * u) return -(MGSTRIDE - 1);
        else                 return -MGSTRIDE;
    } else if (u < 0.f) {
        float t = -u;
        if (v <= c1 * t)     return 1;
        else if (v > c2 * t) return -MGSTRIDE;
        else                 return -(MGSTRIDE + 1);
    }
    return -MGSTRIDE;
}

__global__ void k_colsobel() {
    __shared__ __align__(16) float sA[T1R * T1C];   // raw; later mag^2 (stride 36)
    __shared__ __align__(16) float sS[SSR * T1C];   // smoothed
    __shared__ signed char sB[TILE_H * 32];
    int tx = threadIdx.x, ty = threadIdx.y;
    int tid = ty * 32 + tx;
    int c0 = blockIdx.x * 32;
    int r0 = blockIdx.y * TILE_H;
    int n = blockIdx.z;
    const float* src = g_t1 + (size_t)n * HW;

    bool interior = (r0 != 0) && (r0 != H - TILE_H) && (c0 != 0) && (c0 != W - 32);
    if (interior) {
        const float* base = src + (size_t)(r0 - 10) * W + (c0 - 4);
        for (int i = tid; i < T1R * 10; i += 256) {
            int rr = i / 10, q = i - rr * 10;
            *reinterpret_cast<float4*>(sA + rr * T1C + q * 4) =
                *reinterpret_cast<const float4*>(base + (size_t)rr * W + q * 4);
        }
    } else {
        for (int i = tid; i < T1R * T1C; i += 256) {
            int rr = i / T1C, cc = i - rr * T1C;
            int gi = reflect_idx(r0 - 10 + rr, H);
            int gj = reflect_idx(c0 - 4 + cc, W);
            sA[i] = src[(size_t)gi * W + gj];
        }
    }
    __syncthreads();

    // phase A: vertical blur via register streaming (22 loads -> 6 output rows)
    {
        int q = tid % 10;
        int b = tid / 10;
        if (b < 22) {
            const float* p = sA + (6 * b) * T1C + q * 4;
            float acc[6][4];
#pragma unroll
            for (int o = 0; o < 6; o++) { acc[o][0] = acc[o][1] = acc[o][2] = acc[o][3] = 0.f; }
#pragma unroll
            for (int i = 0; i < 22; i++) {
                float4 v = *reinterpret_cast<const float4*>(p + i * T1C);
#pragma unroll
                for (int o = 0; o < 6; o++) {
                    int k = i - o;
                    if (k >= 0 && k < KLEN) {
                        float wk = gw(k);
                        acc[o][0] += wk * v.x; acc[o][1] += wk * v.y;
                        acc[o][2] += wk * v.z; acc[o][3] += wk * v.w;
                    }
                }
            }
            float* d = sS + (6 * b) * T1C + q * 4;
#pragma unroll
            for (int o = 0; o < 6; o++)
                *reinterpret_cast<float4*>(d + o * T1C) =
                    make_float4(acc[o][0], acc[o][1], acc[o][2], acc[o][3]);
        }
    }
    __syncthreads();

    // phase B: mag^2 + direction via 3x3 rolling window (3 loads/px)
    {
        int c = tid % 34;
        int b = tid / 34;
        if (b < 7) {
            int rstart = 19 * b;
            const float* p = sS + rstart * T1C + c + 2;
            float a0 = p[0], a1 = p[1], a2 = p[2];
            float b0 = p[T1C], b1 = p[T1C + 1], b2 = p[T1C + 2];
#pragma unroll
            for (int r = 0; r < 19; r++) {
                int rm = rstart + r;
                if (rm < 130) {
                    const float* pr = p + (r + 2) * T1C;
                    float e0 = pr[0], e1 = pr[1], e2 = pr[2];
                    float gx = (a2 - a0) + 2.f * (b2 - b0) + (e2 - e0);
                    float gy = (e0 + 2.f * e1 + e2) - (a0 + 2.f * a1 + a2);
                    sA[rm * MGSTRIDE + c] = gx * gx + gy * gy;
                    if (rm >= 1 && rm <= TILE_H && c >= 1 && c <= 32)
                        sB[(rm - 1) * 32 + (c - 1)] = dir_off(gx, gy);
                    a0 = b0; a1 = b1; a2 = b2;
                    b0 = e0; b1 = e1; b2 = e2;
                }
            }
        }
    }
    __syncthreads();

    // border zeroing only on border tiles (block-uniform predicate)
    if (!interior) {
        if (r0 == 0 && tid < 34) sA[tid] = 0.f;
        if (r0 == H - TILE_H && tid < 34) sA[129 * MGSTRIDE + tid] = 0.f;
        if (c0 == 0) { for (int i = tid; i < 130; i += 256) sA[i * MGSTRIDE] = 0.f; }
        if (c0 == W - 32) { for (int i = tid; i < 130; i += 256) sA[i * MGSTRIDE + 33] = 0.f; }
        __syncthreads();
    }

    const float TH2 = 0.04f;
    const float TL2 = 0.01f;
    unsigned int* S32 = reinterpret_cast<unsigned int*>(g_strong64);
    unsigned int* W32 = reinterpret_cast<unsigned int*>(g_weak64);
    size_t base = (size_t)n * (HW / 32) + (size_t)blockIdx.x;
#pragma unroll
    for (int s = 0; s < 16; s++) {
        int lr = ty * 16 + s;
        int ci = (lr + 1) * MGSTRIDE + (tx + 1);
        float mc = sA[ci];
        int off = sB[lr * 32 + tx];
        bool keep = (mc >= sA[ci + off]) && (mc >= sA[ci - off]);
        bool strong = keep && (mc > TH2);
        bool weak = keep && (mc > TL2);
        unsigned ws = __ballot_sync(0xffffffffu, strong);
        unsigned ww = __ballot_sync(0xffffffffu, weak);
        if (tx == 0) {
            size_t widx = base + (size_t)(r0 + lr) * WW32;
            S32[widx] = ws;
            W32[widx] = ww;
        }
    }
}

// ---------------- hysteresis: full-height strips, single pass ----------------
__device__ __forceinline__ ull rowfill(ull s, ull w) {
    ull up = ((w + s) ^ w) & w;
    ull rs = __brevll(s), rwv = __brevll(w);
    ull dn = __brevll(((rwv + rs) ^ rwv) & rwv);
    return s | up | dn;
}
#define HHX(v) ((v) | ((v) << 1) | ((v) >> 1))

__global__ void k_hyst() {
    const int bx = blockIdx.x;
    const int n = blockIdx.y;
    const int t = threadIdx.x;

    __shared__ ull sTop[2][256], sBot[2][256];
    __shared__ unsigned char lbs[1026], rbs[1026];

    ull* S = g_strong64 + (size_t)n * (HW / 64);
    const ull* Wk = g_weak64 + (size_t)n * (HW / 64);

    int gr0 = t * 4;
    ull s[4], w[4];
#pragma unroll
    for (int j = 0; j < 4; j++) {
        size_t off = (size_t)(gr0 + j) * WW64 + bx;
        s[j] = S[off];
        w[j] = Wk[off];
        lbs[gr0 + j + 1] = (bx > 0)        ? (unsigned char)(S[off - 1] >> 63) : 0;
        rbs[gr0 + j + 1] = (bx < WW64 - 1) ? (unsigned char)(S[off + 1] & 1ULL) : 0;
    }
    if (t == 0) { lbs[0] = rbs[0] = lbs[1025] = rbs[1025] = 0; }
    sTop[0][t] = s[0]; sBot[0][t] = s[3];
    __syncthreads();

    ull LR[4];
#pragma unroll
    for (int j = 0; j < 4; j++) {
        int i = gr0 + j;
        unsigned l = (unsigned)(lbs[i] | lbs[i + 1] | lbs[i + 2]);
        unsigned r = (unsigned)(rbs[i] | rbs[i + 1] | rbs[i + 2]);
        LR[j] = (ull)(l & 1u) | ((ull)(r & 1u) << 63);
    }

    int any = 0;
    int pb = 0;
    while (true) {
        ull above = (t > 0)   ? sBot[pb][t - 1] : 0ULL;
        ull below = (t < 255) ? sTop[pb][t + 1] : 0ULL;
        ull o0 = s[0], o1 = s[1], o2 = s[2], o3 = s[3];
        s[0] |= (HHX(above) | HHX(s[0]) | HHX(s[1]) | LR[0]) & w[0]; s[0] = rowfill(s[0], w[0]);
        s[1] |= (HHX(s[0])  | HHX(s[1]) | HHX(s[2]) | LR[1]) & w[1]; s[1] = rowfill(s[1], w[1]);
        s[2] |= (HHX(s[1])  | HHX(s[2]) | HHX(s[3]) | LR[2]) & w[2]; s[2] = rowfill(s[2], w[2]);
        s[3] |= (HHX(s[2])  | HHX(s[3]) | HHX(below)| LR[3]) & w[3]; s[3] = rowfill(s[3], w[3]);
        s[2] |= (HHX(s[1]) | HHX(s[2]) | HHX(s[3]) | LR[2]) & w[2]; s[2] = rowfill(s[2], w[2]);
        s[1] |= (HHX(s[0]) | HHX(s[1]) | HHX(s[2]) | LR[1]) & w[1]; s[1] = rowfill(s[1], w[1]);
        s[0] |= (HHX(above)| HHX(s[0]) | HHX(s[1]) | LR[0]) & w[0]; s[0] = rowfill(s[0], w[0]);
        int ch = (s[0] != o0) | (s[1] != o1) | (s[2] != o2) | (s[3] != o3);
        any |= ch;
        sTop[pb ^ 1][t] = s[0]; sBot[pb ^ 1][t] = s[3];
        pb ^= 1;
        if (!__syncthreads_or(ch)) break;
    }

    if (any) {
#pragma unroll
        for (int j = 0; j < 4; j++) S[(size_t)(gr0 + j) * WW64 + bx] = s[j];
    }
}

// ---------------- loss: mask register reuse over 4 images/thread ----------------
#define LOSS_BLOCKS 512
__global__ void k_loss(const float* __restrict__ y, const float* __restrict__ mask,
                       float* __restrict__ out) {
    const unsigned int* S32 = reinterpret_cast<const unsigned int*>(g_strong64);
    int gid = blockIdx.x * 256 + threadIdx.x;
    int wp = gid & 32767;
    int grp = gid >> 15;
    const float4* m4 = reinterpret_cast<const float4*>(mask + wp * 32);
    float4 mm[8];
#pragma unroll
    for (int j = 0; j < 8; j++) mm[j] = m4[j];

    float acc = 0.f;
#pragma unroll
    for (int g = 0; g < 4; g++) {
        int n = grp * 4 + g;
        unsigned int bits = S32[n * (HW / 32) + wp];
        const float4* y4 = reinterpret_cast<const float4*>(y + (size_t)n * HW + wp * 32);
#pragma unroll
        for (int j = 0; j < 8; j++) {
            float4 yy = y4[j];
            unsigned int b = bits >> (j * 4);
            float p0 = yy.x * mm[j].x, p1 = yy.y * mm[j].y;
            float p2 = yy.z * mm[j].z, p3 = yy.w * mm[j].w;
            acc += (b & 1u)        ? fabsf(mm[j].x - p0) : p0;
            acc += ((b >> 1) & 1u) ? fabsf(mm[j].y - p1) : p1;
            acc += ((b >> 2) & 1u) ? fabsf(mm[j].z - p2) : p2;
            acc += ((b >> 3) & 1u) ? fabsf(mm[j].w - p3) : p3;
        }
    }
#pragma unroll
    for (int off = 16; off; off >>= 1) acc += __shfl_down_sync(0xffffffffu, acc, off);
    __shared__ float sred[8];
    int lane = threadIdx.x & 31, wid = threadIdx.x >> 5;
    if (lane == 0) sred[wid] = acc;
    __syncthreads();
    if (wid == 0) {
        acc = (lane < 8) ? sred[lane] : 0.f;
#pragma unroll
        for (int off = 4; off; off >>= 1) acc += __shfl_down_sync(0xffffffffu, acc, off);
        if (lane == 0) atomicAdd(&g_acc, (double)acc);
    }
    if (threadIdx.x == 0) {
        __threadfence();
        unsigned int ticket = atomicAdd(&g_ticket, 1u);
        if (ticket == gridDim.x - 1) {
            g_ticket = 0;
            double v = atomicAdd(&g_acc, 0.0);
            out[0] = (float)(v * (1.0 / (double)HW));
        }
    }
}

// ---------------- launch ----------------
extern "C" void kernel_launch(void* const* d_in, const int* in_sizes, int n_in,
                              void* d_out, int out_size) {
    const float* x = nullptr;
    const float* y = nullptr;
    const float* mask = nullptr;
    for (int i = 0; i < n_in; i++) {
        if (in_sizes[i] == HW && mask == nullptr) mask = (const float*)d_in[i];
        else if (x == nullptr) x = (const float*)d_in[i];
        else if (y == nullptr) y = (const float*)d_in[i];
    }

    k_rowblur<<<dim3(H / RB_ROWS, N_IMG), 256>>>(x);
    k_colsobel<<<dim3(W / 32, H / TILE_H, N_IMG), dim3(32, 8)>>>();
    k_hyst<<<dim3(WW64, N_IMG), 256>>>();
    k_loss<<<LOSS_BLOCKS, 256>>>(y, mask, (float*)d_out);
}